// round 2
// baseline (speedup 1.0000x reference)
#include <cuda_runtime.h>
#include <cuda_bf16.h>
#include <cstdint>

// Inputs (metadata order):
//   d_in[0] = x      float32 [262144]   (1 MB, random-gathered -> keep in L1)
//   d_in[1] = A_vals float32 [NNZ]      (streamed once -> evict-first)
//   d_in[2] = A_rows int32   [NNZ]      (streamed once -> evict-first)
//   d_in[3] = A_cols int32   [NNZ]      (streamed once -> evict-first)
// Output: float32 [262144]

// x gather with evict_last: keep the 1MB x working set resident in L1 as much
// as possible while the 100MB index/value stream passes through evict-first.
__device__ __forceinline__ float ldg_x(const float* p) {
    float v;
    asm volatile("ld.global.nc.L1::evict_last.f32 %0, [%1];" : "=f"(v) : "l"(p));
    return v;
}

__global__ void __launch_bounds__(256) coo_spmv_kernel(
    const float*  __restrict__ x,
    const float4* __restrict__ vals4,
    const int4*   __restrict__ rows4,
    const int4*   __restrict__ cols4,
    float*        __restrict__ out,
    int nnz4)
{
    int i = blockIdx.x * blockDim.x + threadIdx.x;
    if (i >= nnz4) return;

    // Streaming loads: evict-first so they don't thrash x's L1 residency.
    float4 v = __ldcs(&vals4[i]);
    int4   r = __ldcs(&rows4[i]);
    int4   c = __ldcs(&cols4[i]);

    // Random gathers from L1/L2-resident x (evict_last policy).
    float x0 = ldg_x(&x[c.x]);
    float x1 = ldg_x(&x[c.y]);
    float x2 = ldg_x(&x[c.z]);
    float x3 = ldg_x(&x[c.w]);

    // Scatter-add: return unused -> RED.E.ADD.F32 at L2.
    atomicAdd(&out[r.x], v.x * x0);
    atomicAdd(&out[r.y], v.y * x1);
    atomicAdd(&out[r.z], v.z * x2);
    atomicAdd(&out[r.w], v.w * x3);
}

// Tail handler for nnz not divisible by 4 (unused for this shape, kept safe).
__global__ void coo_spmv_tail_kernel(
    const float* __restrict__ x,
    const float* __restrict__ vals,
    const int*   __restrict__ rows,
    const int*   __restrict__ cols,
    float*       __restrict__ out,
    int start, int nnz)
{
    int i = start + blockIdx.x * blockDim.x + threadIdx.x;
    if (i < nnz) {
        atomicAdd(&out[rows[i]], vals[i] * __ldg(&x[cols[i]]));
    }
}

extern "C" void kernel_launch(void* const* d_in, const int* in_sizes, int n_in,
                              void* d_out, int out_size) {
    const float* x    = (const float*)d_in[0];
    const float* vals = (const float*)d_in[1];
    const int*   rows = (const int*)d_in[2];
    const int*   cols = (const int*)d_in[3];
    float* out = (float*)d_out;

    const int nnz = in_sizes[1];

    // Zero-init output (harness poisons it). Memset node: cheaper than a kernel.
    cudaMemsetAsync(out, 0, (size_t)out_size * sizeof(float), 0);

    // Main vectorized COO pass.
    int nnz4 = nnz / 4;
    if (nnz4 > 0) {
        int threads = 256;
        int blocks = (nnz4 + threads - 1) / threads;
        coo_spmv_kernel<<<blocks, threads>>>(
            x, (const float4*)vals, (const int4*)rows, (const int4*)cols, out, nnz4);
    }

    // Tail (nnz % 4), skipped when empty.
    int tail_start = nnz4 * 4;
    int tail = nnz - tail_start;
    if (tail > 0) {
        coo_spmv_tail_kernel<<<(tail + 255) / 256, 256>>>(
            x, vals, rows, cols, out, tail_start, nnz);
    }
}